// round 13
// baseline (speedup 1.0000x reference)
#include <cuda_runtime.h>
#include <cuda_fp16.h>
#include <mma.h>
#include <cstdint>
#include <cstddef>

using namespace nvcuda;

// ---------------- problem constants ----------------
#define Dc     1024
#define DFFc   4096
#define Ec     16
#define TKc    4
#define STEPSc 4
#define Tc     2048
#define RMAXc  (Tc*TKc)
#define PEREXP (DFFc*Dc)
#define MBLK   8                     // m-blocks per expert (128 rows each; cap 1024)

// ---------------- device scratch ----------------
__device__ __half g_w1q[(size_t)Ec*DFFc*Dc];
__device__ __half g_w2q[(size_t)Ec*DFFc*Dc];
__device__ float  g_gateq[Ec*Dc];
__device__ float  g_g1[Ec];
__device__ float  g_g2[Ec];
__device__ float  g_part[32*1024];
__device__ float  g_state[Tc*Dc];
__device__ __half g_ctx_hi[Tc*Dc];
__device__ __half g_ctx_lo[Tc*Dc];
__device__ __half g_h_hi[(size_t)RMAXc*DFFc];
__device__ __half g_h_lo[(size_t)RMAXc*DFFc];
__device__ float  g_osl[(size_t)RMAXc*Dc];
__device__ int    g_list[Ec*Tc];
__device__ int    g_sel[Tc*TKc];
__device__ int    g_cnt[Ec];        // zero at load; reset by every combine (replay-safe)

// ---------------- async-copy helpers ----------------
__device__ __forceinline__ uint32_t s2u(const void* p) {
    return (uint32_t)__cvta_generic_to_shared(p);
}
#define CP16(dst, src) \
    asm volatile("cp.async.cg.shared.global [%0], [%1], 16;" \
                 :: "r"(dst), "l"((const void*)(src)) : "memory")
#define CP_COMMIT() asm volatile("cp.async.commit_group;" ::: "memory")
#define CP_WAIT0()  asm volatile("cp.async.wait_group 0;" ::: "memory")

// ---------------- quantization ----------------
__global__ void abs_partial_kernel(const float* __restrict__ w1, const float* __restrict__ w2) {
    int chunk = blockIdx.x;
    int tn    = blockIdx.y;
    const float* base = (tn < Ec) ? (w1 + (size_t)tn * PEREXP)
                                  : (w2 + (size_t)(tn - Ec) * PEREXP);
    base += (size_t)chunk * 4096;
    int tid = threadIdx.x;
    float s = 0.f;
    #pragma unroll
    for (int i = 0; i < 16; i++) s += fabsf(base[tid + i*256]);
    __shared__ float red[256];
    red[tid] = s; __syncthreads();
    for (int st = 128; st > 0; st >>= 1) { if (tid < st) red[tid] += red[tid+st]; __syncthreads(); }
    if (tid == 0) g_part[tn*1024 + chunk] = red[0];
}

// Fused: blocks 0..16383 quantize (each re-reduces its tensor's scale); block 16384 = gate.
__global__ void quant_gate_kernel(const float* __restrict__ w1, const float* __restrict__ w2,
                                  const float* __restrict__ gw) {
    int tid = threadIdx.x;
    __shared__ float red[256];
    __shared__ float sg;
    if (blockIdx.x == 16384) {
        float s = 0.f;
        for (int i = tid; i < Ec*Dc; i += 256) s += fabsf(gw[i]);
        red[tid] = s; __syncthreads();
        for (int st = 128; st > 0; st >>= 1) { if (tid < st) red[tid] += red[tid+st]; __syncthreads(); }
        if (tid == 0) sg = fmaxf(red[0] / (float)(Ec*Dc), 1e-5f);
        __syncthreads();
        float g = sg;
        for (int i = tid; i < Ec*Dc; i += 256) {
            float q = rintf(gw[i] / g);
            g_gateq[i] = fminf(fmaxf(q, -1.f), 1.f);
        }
        return;
    }
    int tn  = blockIdx.x >> 9;
    int seg = blockIdx.x & 511;
    float s = 0.f;
    for (int i = tid; i < 1024; i += 256) s += g_part[tn*1024 + i];
    red[tid] = s; __syncthreads();
    for (int st = 128; st > 0; st >>= 1) { if (tid < st) red[tid] += red[tid+st]; __syncthreads(); }
    if (tid == 0) {
        sg = fmaxf(red[0] / (float)PEREXP, 1e-5f);
        if (seg == 0) { if (tn < Ec) g_g1[tn] = sg; else g_g2[tn - Ec] = sg; }
    }
    __syncthreads();
    float g = sg;
    int e = tn & 15;
    const float* w = (tn < Ec) ? w1 : w2;
    __half* q      = (tn < Ec) ? g_w1q : g_w2q;
    size_t base = (size_t)e * (PEREXP/4) + (size_t)seg * 2048;
    #pragma unroll
    for (int it = 0; it < 8; it++) {
        size_t i = base + tid + it*256;
        float4 v = reinterpret_cast<const float4*>(w)[i];
        float q0 = fminf(fmaxf(rintf(v.x / g), -1.f), 1.f);
        float q1 = fminf(fmaxf(rintf(v.y / g), -1.f), 1.f);
        float q2 = fminf(fmaxf(rintf(v.z / g), -1.f), 1.f);
        float q3 = fminf(fmaxf(rintf(v.w / g), -1.f), 1.f);
        __half2* qo = reinterpret_cast<__half2*>(q) + i*2;
        qo[0] = __floats2half2_rn(q0, q1);
        qo[1] = __floats2half2_rn(q2, q3);
    }
}

// ---------------- routing (step 0 reads x directly) ----------------
__global__ void route_kernel(const float* __restrict__ comp, const float* __restrict__ temb,
                             int step, const float* __restrict__ x) {
    int t = blockIdx.x, tid = threadIdx.x;
    if (!(comp[t] > 0.5f)) {
        #pragma unroll
        for (int i = 0; i < 8; i++) {
            int d = tid + i*128;
            g_ctx_hi[t*Dc + d] = __float2half(0.f);
            g_ctx_lo[t*Dc + d] = __float2half(0.f);
        }
        return;
    }
    const float* src = (step == 0) ? (x + (size_t)t*Dc) : (g_state + (size_t)t*Dc);
    float cx[8];
    #pragma unroll
    for (int i = 0; i < 8; i++) {
        int d = tid + i*128;
        float v = src[d] + temb[step*Dc + d];
        cx[i] = v;
        __half hi = __float2half(v);
        g_ctx_hi[t*Dc + d] = hi;
        g_ctx_lo[t*Dc + d] = __float2half(v - __half2float(hi));
    }
    float p[16];
    #pragma unroll
    for (int e = 0; e < 16; e++) p[e] = 0.f;
    #pragma unroll
    for (int i = 0; i < 8; i++) {
        int d = tid + i*128;
        #pragma unroll
        for (int e = 0; e < 16; e++) p[e] += cx[i] * g_gateq[e*Dc + d];
    }
    __shared__ float wsum[4][16];
    __shared__ float slog[16];
    int lane = tid & 31, wp = tid >> 5;
    #pragma unroll
    for (int e = 0; e < 16; e++) {
        float s = p[e];
        for (int o = 16; o > 0; o >>= 1) s += __shfl_down_sync(0xffffffffu, s, o);
        if (lane == 0) wsum[wp][e] = s;
    }
    __syncthreads();
    if (tid < 16) slog[tid] = wsum[0][tid] + wsum[1][tid] + wsum[2][tid] + wsum[3][tid];
    __syncthreads();
    if (tid == 0) {
        float lg[16];
        #pragma unroll
        for (int e = 0; e < 16; e++) lg[e] = slog[e];
        for (int k = 0; k < TKc; k++) {
            int best = 0; float bv = lg[0];
            for (int e = 1; e < 16; e++) if (lg[e] > bv) { bv = lg[e]; best = e; }
            g_sel[t*TKc + k] = best;
            lg[best] = -3.4e38f;
            int pos = atomicAdd(&g_cnt[best], 1);
            g_list[best*Tc + pos] = t*TKc + k;
        }
    }
}

// ==================================================================
// wmma GEMM: 128(M) x 256(N) block tile, K-chunk 64, 512 threads,
// 16 warps in 4(M)x4(N), warp tile 32x64 (0.5 frag loads per MMA).
// hi+lo limbs both accumulate into one f32 accumulator set.
// 2-buffer cp.async pipeline, one __syncthreads per chunk.
// Per buffer: AsHi 18432 + AsLo 18432 + Bs 36864 = 73728 B; x2 = 147456.
// 1 CTA/SM but 16 warps/SM (same warp count as 2x8-warp CTAs).
// W slab re-read halved vs M=64 tiles.
// ==================================================================
#define SM_AHI 0
#define SM_ALO 18432
#define SM_B   36864
#define BUF_BYTES 73728
#define DSM_BYTES (2*BUF_BYTES)      // 147456

// ---------------- FFN1: H = gelu(g1 * ctx @ W1^T) ----------------
__global__ void __launch_bounds__(512, 1) ffn1_kernel() {
    extern __shared__ char dsm[];
    __shared__ int rows[128];
    __shared__ int s_off;

    int e   = blockIdx.z;
    int cnt = g_cnt[e];
    int m0  = blockIdx.x * 128;
    if (m0 >= cnt) return;
    int n0  = blockIdx.y * 256;
    int tid = threadIdx.x;

    if (tid < 128) rows[tid] = (m0 + tid < cnt) ? g_list[e*Tc + m0 + tid] : -1;
    if (tid == 0) {
        int r = 0;
        for (int i = 0; i < e; i++) r += g_cnt[i];
        s_off = r;
    }
    __syncthreads();

    const __half* W = g_w1q + (size_t)e*DFFc*Dc + (size_t)n0*Dc;

    auto stage = [&](int chunk, char* buf) {
        int k0 = chunk << 6;
        uint32_t aHi = s2u(buf + SM_AHI);
        uint32_t aLo = s2u(buf + SM_ALO);
        uint32_t bS  = s2u(buf + SM_B);
        #pragma unroll
        for (int it = 0; it < 2; it++) {           // A hi/lo: 128x64 halves = 1024 granules each
            int u = tid + (it << 9);
            int r = u >> 3, gi = u & 7;
            uint32_t off = (uint32_t)(r*144 + gi*16);
            int code = rows[r];
            int tok = code >= 0 ? (code >> 2) : 0;
            CP16(aHi + off, g_ctx_hi + (size_t)tok*Dc + k0 + (gi<<3));
            CP16(aLo + off, g_ctx_lo + (size_t)tok*Dc + k0 + (gi<<3));
        }
        #pragma unroll
        for (int it = 0; it < 4; it++) {           // B: 256x64 halves = 2048 granules
            int u = tid + (it << 9);
            int r = u >> 3, gi = u & 7;
            uint32_t off = (uint32_t)(r*144 + gi*16);
            CP16(bS + off, W + (size_t)r*Dc + k0 + (gi<<3));
        }
    };

    int warp = tid >> 5;
    int wm = warp >> 2, wn = warp & 3;             // 4(M) x 4(N); warp tile 32x64
    wmma::fragment<wmma::accumulator,16,16,16,float> acc[2][4];
    #pragma unroll
    for (int i = 0; i < 2; i++)
        #pragma unroll
        for (int j = 0; j < 4; j++) wmma::fill_fragment(acc[i][j], 0.f);

    stage(0, dsm); CP_COMMIT();

    const int KC = Dc / 64;   // 16
    for (int c0 = 0; c0 < KC; c0++) {
        CP_WAIT0();
        __syncthreads();
        if (c0 + 1 < KC) { stage(c0 + 1, dsm + (size_t)((c0+1)&1)*BUF_BYTES); CP_COMMIT(); }
        char* cur = dsm + (size_t)(c0 & 1) * BUF_BYTES;
        __half (*AsHi)[72] = (__half(*)[72])(cur + SM_AHI);
        __half (*AsLo)[72] = (__half(*)[72])(cur + SM_ALO);
        __half (*Bs)[72]   = (__half(*)[72])(cur + SM_B);
        #pragma unroll
        for (int kk = 0; kk < 64; kk += 16) {
            wmma::fragment<wmma::matrix_a,16,16,16,__half,wmma::row_major> aHi[2], aLo[2];
            #pragma unroll
            for (int i = 0; i < 2; i++) {
                wmma::load_matrix_sync(aHi[i], &AsHi[wm*32 + i*16][kk], 72);
                wmma::load_matrix_sync(aLo[i], &AsLo[wm*32 + i*16][kk], 72);
            }
            #pragma unroll
            for (int j = 0; j < 4; j++) {
                wmma::fragment<wmma::matrix_b,16,16,16,__half,wmma::col_major> b;
                wmma::load_matrix_sync(b, &Bs[wn*64 + j*16][kk], 72);
                #pragma unroll
                for (int i = 0; i < 2; i++) {
                    wmma::mma_sync(acc[i][j], aHi[i], b, acc[i][j]);
                    wmma::mma_sync(acc[i][j], aLo[i], b, acc[i][j]);
                }
            }
        }
    }
    __syncthreads();

    // epilogue via smem: Cs[128][260] f32 = 133120 B (fits in 147456)
    float (*Cs)[260] = (float(*)[260])dsm;
    #pragma unroll
    for (int i = 0; i < 2; i++)
        #pragma unroll
        for (int j = 0; j < 4; j++)
            wmma::store_matrix_sync(&Cs[wm*32 + i*16][wn*64 + j*16], acc[i][j], 260, wmma::mem_row_major);
    __syncthreads();

    float g1 = g_g1[e];
    int off  = s_off;
    for (int idx = tid; idx < 128*256; idx += 512) {
        int r = idx >> 8, c = idx & 255;
        if (rows[r] < 0) continue;
        float v  = g1 * Cs[r][c];
        float ge = 0.5f * v * (1.0f + erff(v * 0.7071067811865476f));
        __half hi = __float2half(ge);
        size_t o  = (size_t)(off + m0 + r)*DFFc + n0 + c;
        g_h_hi[o] = hi;
        g_h_lo[o] = __float2half(ge - __half2float(hi));
    }
}

// ---------------- FFN2: O = g2 * H @ W2^T ----------------
__global__ void __launch_bounds__(512, 1) ffn2_kernel() {
    extern __shared__ char dsm[];
    __shared__ int slots[128];
    __shared__ int s_off;

    int e   = blockIdx.z;
    int cnt = g_cnt[e];
    int m0  = blockIdx.x * 128;
    if (m0 >= cnt) return;
    int n0  = blockIdx.y * 256;
    int tid = threadIdx.x;

    if (tid < 128) slots[tid] = (m0 + tid < cnt) ? g_list[e*Tc + m0 + tid] : -1;
    if (tid == 0) {
        int r = 0;
        for (int i = 0; i < e; i++) r += g_cnt[i];
        s_off = r;
    }
    __syncthreads();
    int off = s_off;
    int lastrow = off + cnt - 1;

    const __half* W = g_w2q + (size_t)e*DFFc*Dc + (size_t)n0*DFFc;

    auto stage = [&](int chunk, char* buf) {
        int k0 = chunk << 6;
        uint32_t aHi = s2u(buf + SM_AHI);
        uint32_t aLo = s2u(buf + SM_ALO);
        uint32_t bS  = s2u(buf + SM_B);
        #pragma unroll
        for (int it = 0; it < 2; it++) {
            int u = tid + (it << 9);
            int r = u >> 3, gi = u & 7;
            uint32_t off2 = (uint32_t)(r*144 + gi*16);
            int src = off + m0 + r; if (src > lastrow) src = lastrow;
            CP16(aHi + off2, g_h_hi + (size_t)src*DFFc + k0 + (gi<<3));
            CP16(aLo + off2, g_h_lo + (size_t)src*DFFc + k0 + (gi<<3));
        }
        #pragma unroll
        for (int it = 0; it < 4; it++) {
            int u = tid + (it << 9);
            int r = u >> 3, gi = u & 7;
            uint32_t off2 = (uint32_t)(r*144 + gi*16);
            CP16(bS + off2, W + (size_t)r*DFFc + k0 + (gi<<3));
        }
    };

    int warp = tid >> 5;
    int wm = warp >> 2, wn = warp & 3;
    wmma::fragment<wmma::accumulator,16,16,16,float> acc[2][4];
    #pragma unroll
    for (int i = 0; i < 2; i++)
        #pragma unroll
        for (int j = 0; j < 4; j++) wmma::fill_fragment(acc[i][j], 0.f);

    stage(0, dsm); CP_COMMIT();

    const int KC = DFFc / 64;   // 64
    for (int c0 = 0; c0 < KC; c0++) {
        CP_WAIT0();
        __syncthreads();
        if (c0 + 1 < KC) { stage(c0 + 1, dsm + (size_t)((c0+1)&1)*BUF_BYTES); CP_COMMIT(); }
        char* cur = dsm + (size_t)(c0 & 1) * BUF_BYTES;
        __half (*AsHi)[72] = (__half(*)[72])(cur + SM_AHI);
        __half (*AsLo)[72] = (__half(*)[72])(cur + SM_ALO);
        __half (*Bs)[72]   = (__half(*)[72])(cur + SM_B);
        #pragma unroll
        for (int kk = 0; kk < 64; kk += 16) {
            wmma::fragment<wmma::matrix_a,16,16,16,__half,wmma::row_major> aHi[2], aLo[2];
            #pragma unroll
            for (int i = 0; i < 2; i++) {
                wmma::load_matrix_sync(aHi[i], &AsHi[wm*32 + i*16][kk], 72);
                wmma::load_matrix_sync(aLo[i], &AsLo[wm*32 + i*16][kk], 72);
            }
            #pragma unroll
            for (int j = 0; j < 4; j++) {
                wmma::fragment<wmma::matrix_b,16,16,16,__half,wmma::col_major> b;
                wmma::load_matrix_sync(b, &Bs[wn*64 + j*16][kk], 72);
                #pragma unroll
                for (int i = 0; i < 2; i++) {
                    wmma::mma_sync(acc[i][j], aHi[i], b, acc[i][j]);
                    wmma::mma_sync(acc[i][j], aLo[i], b, acc[i][j]);
                }
            }
        }
    }
    __syncthreads();

    float (*Cs)[260] = (float(*)[260])dsm;
    #pragma unroll
    for (int i = 0; i < 2; i++)
        #pragma unroll
        for (int j = 0; j < 4; j++)
            wmma::store_matrix_sync(&Cs[wm*32 + i*16][wn*64 + j*16], acc[i][j], 260, wmma::mem_row_major);
    __syncthreads();

    float g2 = g_g2[e];
    for (int idx = tid; idx < 128*256; idx += 512) {
        int r = idx >> 8, c = idx & 255;
        int sc = slots[r];
        if (sc < 0) continue;
        g_osl[(size_t)sc*Dc + n0 + c] = g2 * Cs[r][c];
    }
}

// ---------------- combine (resets g_cnt; final step writes out) ----------------
__global__ void combine_kernel(const float* __restrict__ comp, const float* __restrict__ normw,
                               const float* __restrict__ x, float* __restrict__ out, int mode) {
    int t = blockIdx.x, tid = threadIdx.x;
    if (t == 0 && tid < Ec) g_cnt[tid] = 0;
    if (!(comp[t] > 0.5f)) {
        if (mode == 1) {
            #pragma unroll
            for (int i = 0; i < 4; i++) {
                int d = tid + i*256;
                out[(size_t)t*Dc + d] = x[(size_t)t*Dc + d];
            }
        }
        return;
    }
    int se[4];
    #pragma unroll
    for (int k = 0; k < 4; k++) se[k] = g_sel[t*4 + k];
    int ord[4] = {0,1,2,3};
    #pragma unroll
    for (int a = 0; a < 3; a++)
        #pragma unroll
        for (int b = a+1; b < 4; b++)
            if (se[ord[b]] < se[ord[a]]) { int tmp = ord[a]; ord[a] = ord[b]; ord[b] = tmp; }
    float y[4]; float ss = 0.f;
    #pragma unroll
    for (int i = 0; i < 4; i++) {
        int d = tid + i*256;
        float s = g_osl[(size_t)(t*4 + ord[0])*Dc + d];
        s += g_osl[(size_t)(t*4 + ord[1])*Dc + d];
        s += g_osl[(size_t)(t*4 + ord[2])*Dc + d];
        s += g_osl[(size_t)(t*4 + ord[3])*Dc + d];
        float prev = (mode == 2) ? x[(size_t)t*Dc + d] : g_state[(size_t)t*Dc + d];
        float v = s + prev;
        y[i] = v; ss += v*v;
    }
    int lane = tid & 31, wp = tid >> 5;
    for (int o = 16; o > 0; o >>= 1) ss += __shfl_down_sync(0xffffffffu, ss, o);
    __shared__ float ws[8];
    __shared__ float svar;
    if (lane == 0) ws[wp] = ss;
    __syncthreads();
    if (tid == 0) {
        float s2 = 0.f;
        for (int w = 0; w < 8; w++) s2 += ws[w];
        svar = s2 * (1.f / (float)Dc);
    }
    __syncthreads();
    float rinv = rsqrtf(svar + 1e-6f);
    #pragma unroll
    for (int i = 0; i < 4; i++) {
        int d = tid + i*256;
        float val = normw[d] * y[i] * rinv;
        if (mode == 1) out[(size_t)t*Dc + d] = val;
        else           g_state[(size_t)t*Dc + d] = val;
    }
}

// ---------------- launch ----------------
// combine mode: 2 = step 0 (residual from x), 0 = middle steps, 1 = final (write out)
extern "C" void kernel_launch(void* const* d_in, const int* in_sizes, int n_in,
                              void* d_out, int out_size) {
    const float* x    = (const float*)d_in[0];
    const float* comp = (const float*)d_in[1];
    const float* gw   = (const float*)d_in[2];
    const float* w1   = (const float*)d_in[3];
    const float* w2   = (const float*)d_in[4];
    const float* temb = (const float*)d_in[5];
    const float* nw   = (const float*)d_in[6];
    float* out = (float*)d_out;

    cudaFuncSetAttribute(ffn1_kernel, cudaFuncAttributeMaxDynamicSharedMemorySize, DSM_BYTES);
    cudaFuncSetAttribute(ffn2_kernel, cudaFuncAttributeMaxDynamicSharedMemorySize, DSM_BYTES);

    abs_partial_kernel<<<dim3(1024, 32), 256>>>(w1, w2);
    quant_gate_kernel<<<16385, 256>>>(w1, w2, gw);

    for (int s = 0; s < STEPSc; s++) {
        route_kernel<<<Tc, 128>>>(comp, temb, s, x);
        ffn1_kernel<<<dim3(MBLK, DFFc/256, Ec), 512, DSM_BYTES>>>();
        ffn2_kernel<<<dim3(MBLK, Dc/256, Ec), 512, DSM_BYTES>>>();
        int mode = (s == 0) ? 2 : (s == STEPSc-1 ? 1 : 0);
        combine_kernel<<<Tc, 256>>>(comp, nw, x, out, mode);
    }
}

// round 14
// speedup vs baseline: 1.5091x; 1.5091x over previous
#include <cuda_runtime.h>
#include <cuda_fp16.h>
#include <mma.h>
#include <cstdint>
#include <cstddef>

using namespace nvcuda;

// ---------------- problem constants ----------------
#define Dc     1024
#define DFFc   4096
#define Ec     16
#define TKc    4
#define STEPSc 4
#define Tc     2048
#define RMAXc  (Tc*TKc)
#define PEREXP (DFFc*Dc)
#define MBLK   16                    // m-blocks per expert (64 rows each; cap 1024)

// ---------------- device scratch ----------------
__device__ __half g_w1q[(size_t)Ec*DFFc*Dc];
__device__ __half g_w2q[(size_t)Ec*DFFc*Dc];
__device__ float  g_gateq[Ec*Dc];
__device__ float  g_g1[Ec];
__device__ float  g_g2[Ec];
__device__ float  g_part[32*1024];
__device__ float  g_state[Tc*Dc];
__device__ __half g_ctx_hi[Tc*Dc];
__device__ __half g_ctx_lo[Tc*Dc];
__device__ __half g_h_hi[(size_t)RMAXc*DFFc];
__device__ __half g_h_lo[(size_t)RMAXc*DFFc];
__device__ float  g_osl[(size_t)RMAXc*Dc];
__device__ int    g_list[Ec*Tc];
__device__ int    g_sel[Tc*TKc];
__device__ int    g_cnt[Ec];        // zero at load; reset by every combine (replay-safe)

// ---------------- async-copy helpers ----------------
__device__ __forceinline__ uint32_t s2u(const void* p) {
    return (uint32_t)__cvta_generic_to_shared(p);
}
#define CP16(dst, src) \
    asm volatile("cp.async.cg.shared.global [%0], [%1], 16;" \
                 :: "r"(dst), "l"((const void*)(src)) : "memory")
#define CP_COMMIT() asm volatile("cp.async.commit_group;" ::: "memory")
#define CP_WAIT0()  asm volatile("cp.async.wait_group 0;" ::: "memory")

// ---------------- quantization ----------------
__global__ void abs_partial_kernel(const float* __restrict__ w1, const float* __restrict__ w2) {
    int chunk = blockIdx.x;
    int tn    = blockIdx.y;
    const float* base = (tn < Ec) ? (w1 + (size_t)tn * PEREXP)
                                  : (w2 + (size_t)(tn - Ec) * PEREXP);
    base += (size_t)chunk * 4096;
    int tid = threadIdx.x;
    float s = 0.f;
    #pragma unroll
    for (int i = 0; i < 16; i++) s += fabsf(base[tid + i*256]);
    __shared__ float red[256];
    red[tid] = s; __syncthreads();
    for (int st = 128; st > 0; st >>= 1) { if (tid < st) red[tid] += red[tid+st]; __syncthreads(); }
    if (tid == 0) g_part[tn*1024 + chunk] = red[0];
}

// Fused: blocks 0..16383 quantize (each re-reduces its tensor's scale); block 16384 = gate.
__global__ void quant_gate_kernel(const float* __restrict__ w1, const float* __restrict__ w2,
                                  const float* __restrict__ gw) {
    int tid = threadIdx.x;
    __shared__ float red[256];
    __shared__ float sg;
    if (blockIdx.x == 16384) {
        float s = 0.f;
        for (int i = tid; i < Ec*Dc; i += 256) s += fabsf(gw[i]);
        red[tid] = s; __syncthreads();
        for (int st = 128; st > 0; st >>= 1) { if (tid < st) red[tid] += red[tid+st]; __syncthreads(); }
        if (tid == 0) sg = fmaxf(red[0] / (float)(Ec*Dc), 1e-5f);
        __syncthreads();
        float g = sg;
        for (int i = tid; i < Ec*Dc; i += 256) {
            float q = rintf(gw[i] / g);
            g_gateq[i] = fminf(fmaxf(q, -1.f), 1.f);
        }
        return;
    }
    int tn  = blockIdx.x >> 9;
    int seg = blockIdx.x & 511;
    float s = 0.f;
    for (int i = tid; i < 1024; i += 256) s += g_part[tn*1024 + i];
    red[tid] = s; __syncthreads();
    for (int st = 128; st > 0; st >>= 1) { if (tid < st) red[tid] += red[tid+st]; __syncthreads(); }
    if (tid == 0) {
        sg = fmaxf(red[0] / (float)PEREXP, 1e-5f);
        if (seg == 0) { if (tn < Ec) g_g1[tn] = sg; else g_g2[tn - Ec] = sg; }
    }
    __syncthreads();
    float g = sg;
    int e = tn & 15;
    const float* w = (tn < Ec) ? w1 : w2;
    __half* q      = (tn < Ec) ? g_w1q : g_w2q;
    size_t base = (size_t)e * (PEREXP/4) + (size_t)seg * 2048;
    #pragma unroll
    for (int it = 0; it < 8; it++) {
        size_t i = base + tid + it*256;
        float4 v = reinterpret_cast<const float4*>(w)[i];
        float q0 = fminf(fmaxf(rintf(v.x / g), -1.f), 1.f);
        float q1 = fminf(fmaxf(rintf(v.y / g), -1.f), 1.f);
        float q2 = fminf(fmaxf(rintf(v.z / g), -1.f), 1.f);
        float q3 = fminf(fmaxf(rintf(v.w / g), -1.f), 1.f);
        __half2* qo = reinterpret_cast<__half2*>(q) + i*2;
        qo[0] = __floats2half2_rn(q0, q1);
        qo[1] = __floats2half2_rn(q2, q3);
    }
}

// ---------------- routing (step 0 reads x directly) ----------------
__global__ void route_kernel(const float* __restrict__ comp, const float* __restrict__ temb,
                             int step, const float* __restrict__ x) {
    int t = blockIdx.x, tid = threadIdx.x;
    if (!(comp[t] > 0.5f)) {
        #pragma unroll
        for (int i = 0; i < 8; i++) {
            int d = tid + i*128;
            g_ctx_hi[t*Dc + d] = __float2half(0.f);
            g_ctx_lo[t*Dc + d] = __float2half(0.f);
        }
        return;
    }
    const float* src = (step == 0) ? (x + (size_t)t*Dc) : (g_state + (size_t)t*Dc);
    float cx[8];
    #pragma unroll
    for (int i = 0; i < 8; i++) {
        int d = tid + i*128;
        float v = src[d] + temb[step*Dc + d];
        cx[i] = v;
        __half hi = __float2half(v);
        g_ctx_hi[t*Dc + d] = hi;
        g_ctx_lo[t*Dc + d] = __float2half(v - __half2float(hi));
    }
    float p[16];
    #pragma unroll
    for (int e = 0; e < 16; e++) p[e] = 0.f;
    #pragma unroll
    for (int i = 0; i < 8; i++) {
        int d = tid + i*128;
        #pragma unroll
        for (int e = 0; e < 16; e++) p[e] += cx[i] * g_gateq[e*Dc + d];
    }
    __shared__ float wsum[4][16];
    __shared__ float slog[16];
    int lane = tid & 31, wp = tid >> 5;
    #pragma unroll
    for (int e = 0; e < 16; e++) {
        float s = p[e];
        for (int o = 16; o > 0; o >>= 1) s += __shfl_down_sync(0xffffffffu, s, o);
        if (lane == 0) wsum[wp][e] = s;
    }
    __syncthreads();
    if (tid < 16) slog[tid] = wsum[0][tid] + wsum[1][tid] + wsum[2][tid] + wsum[3][tid];
    __syncthreads();
    if (tid == 0) {
        float lg[16];
        #pragma unroll
        for (int e = 0; e < 16; e++) lg[e] = slog[e];
        for (int k = 0; k < TKc; k++) {
            int best = 0; float bv = lg[0];
            for (int e = 1; e < 16; e++) if (lg[e] > bv) { bv = lg[e]; best = e; }
            g_sel[t*TKc + k] = best;
            lg[best] = -3.4e38f;
            int pos = atomicAdd(&g_cnt[best], 1);
            g_list[best*Tc + pos] = t*TKc + k;
        }
    }
}

// ==================================================================
// wmma GEMM (R11 geometry — validated optimum): 64(M) x 256(N) block,
// K-chunk 64, 8 warps 2(M)x4(N), warp tile 32x64 (0.5 frag loads/MMA).
// hi+lo limbs accumulate into one f32 accumulator set.
// 2-buffer cp.async pipeline, one __syncthreads per chunk.
// Per buffer: AsHi 9216 + AsLo 9216 + Bs 36864 = 55296 B; x2 = 110592.
// 2 CTAs/SM. Vectorized (__half2 / float2) epilogues.
// ==================================================================
#define SM_AHI 0
#define SM_ALO 9216
#define SM_B   18432
#define BUF_BYTES 55296
#define DSM_BYTES (2*BUF_BYTES)      // 110592

// ---------------- FFN1: H = gelu(g1 * ctx @ W1^T) ----------------
__global__ void __launch_bounds__(256, 2) ffn1_kernel() {
    extern __shared__ char dsm[];
    __shared__ int rows[64];
    __shared__ int s_off;

    int e   = blockIdx.z;
    int cnt = g_cnt[e];
    int m0  = blockIdx.x * 64;
    if (m0 >= cnt) return;
    int n0  = blockIdx.y * 256;
    int tid = threadIdx.x;

    if (tid < 64) rows[tid] = (m0 + tid < cnt) ? g_list[e*Tc + m0 + tid] : -1;
    if (tid == 0) {
        int r = 0;
        for (int i = 0; i < e; i++) r += g_cnt[i];
        s_off = r;
    }
    __syncthreads();

    const __half* W = g_w1q + (size_t)e*DFFc*Dc + (size_t)n0*Dc;

    auto stage = [&](int chunk, char* buf) {
        int k0 = chunk << 6;
        uint32_t aHi = s2u(buf + SM_AHI);
        uint32_t aLo = s2u(buf + SM_ALO);
        uint32_t bS  = s2u(buf + SM_B);
        #pragma unroll
        for (int it = 0; it < 2; it++) {           // A hi/lo: 64x64 halves = 512 granules each
            int u = tid + (it << 8);
            int r = u >> 3, gi = u & 7;
            uint32_t off = (uint32_t)(r*144 + gi*16);
            int code = rows[r];
            int tok = code >= 0 ? (code >> 2) : 0;
            CP16(aHi + off, g_ctx_hi + (size_t)tok*Dc + k0 + (gi<<3));
            CP16(aLo + off, g_ctx_lo + (size_t)tok*Dc + k0 + (gi<<3));
        }
        #pragma unroll
        for (int it = 0; it < 8; it++) {           // B: 256x64 halves = 2048 granules
            int u = tid + (it << 8);
            int r = u >> 3, gi = u & 7;
            uint32_t off = (uint32_t)(r*144 + gi*16);
            CP16(bS + off, W + (size_t)r*Dc + k0 + (gi<<3));
        }
    };

    int warp = tid >> 5;
    int wm = warp & 1, wn = warp >> 1;             // 2(M) x 4(N); warp tile 32x64
    wmma::fragment<wmma::accumulator,16,16,16,float> acc[2][4];
    #pragma unroll
    for (int i = 0; i < 2; i++)
        #pragma unroll
        for (int j = 0; j < 4; j++) wmma::fill_fragment(acc[i][j], 0.f);

    stage(0, dsm); CP_COMMIT();

    const int KC = Dc / 64;   // 16
    for (int c0 = 0; c0 < KC; c0++) {
        CP_WAIT0();
        __syncthreads();
        if (c0 + 1 < KC) { stage(c0 + 1, dsm + (size_t)((c0+1)&1)*BUF_BYTES); CP_COMMIT(); }
        char* cur = dsm + (size_t)(c0 & 1) * BUF_BYTES;
        __half (*AsHi)[72] = (__half(*)[72])(cur + SM_AHI);
        __half (*AsLo)[72] = (__half(*)[72])(cur + SM_ALO);
        __half (*Bs)[72]   = (__half(*)[72])(cur + SM_B);
        #pragma unroll
        for (int kk = 0; kk < 64; kk += 16) {
            wmma::fragment<wmma::matrix_a,16,16,16,__half,wmma::row_major> aHi[2], aLo[2];
            #pragma unroll
            for (int i = 0; i < 2; i++) {
                wmma::load_matrix_sync(aHi[i], &AsHi[wm*32 + i*16][kk], 72);
                wmma::load_matrix_sync(aLo[i], &AsLo[wm*32 + i*16][kk], 72);
            }
            #pragma unroll
            for (int j = 0; j < 4; j++) {
                wmma::fragment<wmma::matrix_b,16,16,16,__half,wmma::col_major> b;
                wmma::load_matrix_sync(b, &Bs[wn*64 + j*16][kk], 72);
                #pragma unroll
                for (int i = 0; i < 2; i++) {
                    wmma::mma_sync(acc[i][j], aHi[i], b, acc[i][j]);
                    wmma::mma_sync(acc[i][j], aLo[i], b, acc[i][j]);
                }
            }
        }
    }
    __syncthreads();

    // epilogue via smem: Cs[64][260] f32
    float (*Cs)[260] = (float(*)[260])dsm;
    #pragma unroll
    for (int i = 0; i < 2; i++)
        #pragma unroll
        for (int j = 0; j < 4; j++)
            wmma::store_matrix_sync(&Cs[wm*32 + i*16][wn*64 + j*16], acc[i][j], 260, wmma::mem_row_major);
    __syncthreads();

    float g1 = g_g1[e];
    int off  = s_off;
    // vectorized: 2 adjacent columns per thread -> __half2 stores
    for (int idx = tid; idx < 64*128; idx += 256) {
        int r = idx >> 7, c = (idx & 127) << 1;
        if (rows[r] < 0) continue;
        float v0 = g1 * Cs[r][c];
        float v1 = g1 * Cs[r][c + 1];
        float e0 = 0.5f * v0 * (1.0f + erff(v0 * 0.7071067811865476f));
        float e1 = 0.5f * v1 * (1.0f + erff(v1 * 0.7071067811865476f));
        __half h0 = __float2half(e0), h1 = __float2half(e1);
        size_t o = (size_t)(off + m0 + r)*DFFc + n0 + c;
        *reinterpret_cast<__half2*>(&g_h_hi[o]) = __halves2half2(h0, h1);
        *reinterpret_cast<__half2*>(&g_h_lo[o]) =
            __halves2half2(__float2half(e0 - __half2float(h0)),
                           __float2half(e1 - __half2float(h1)));
    }
}

// ---------------- FFN2: O = g2 * H @ W2^T ----------------
__global__ void __launch_bounds__(256, 2) ffn2_kernel() {
    extern __shared__ char dsm[];
    __shared__ int slots[64];
    __shared__ int s_off;

    int e   = blockIdx.z;
    int cnt = g_cnt[e];
    int m0  = blockIdx.x * 64;
    if (m0 >= cnt) return;
    int n0  = blockIdx.y * 256;
    int tid = threadIdx.x;

    if (tid < 64) slots[tid] = (m0 + tid < cnt) ? g_list[e*Tc + m0 + tid] : -1;
    if (tid == 0) {
        int r = 0;
        for (int i = 0; i < e; i++) r += g_cnt[i];
        s_off = r;
    }
    __syncthreads();
    int off = s_off;
    int lastrow = off + cnt - 1;

    const __half* W = g_w2q + (size_t)e*DFFc*Dc + (size_t)n0*DFFc;

    auto stage = [&](int chunk, char* buf) {
        int k0 = chunk << 6;
        uint32_t aHi = s2u(buf + SM_AHI);
        uint32_t aLo = s2u(buf + SM_ALO);
        uint32_t bS  = s2u(buf + SM_B);
        #pragma unroll
        for (int it = 0; it < 2; it++) {
            int u = tid + (it << 8);
            int r = u >> 3, gi = u & 7;
            uint32_t off2 = (uint32_t)(r*144 + gi*16);
            int src = off + m0 + r; if (src > lastrow) src = lastrow;
            CP16(aHi + off2, g_h_hi + (size_t)src*DFFc + k0 + (gi<<3));
            CP16(aLo + off2, g_h_lo + (size_t)src*DFFc + k0 + (gi<<3));
        }
        #pragma unroll
        for (int it = 0; it < 8; it++) {
            int u = tid + (it << 8);
            int r = u >> 3, gi = u & 7;
            uint32_t off2 = (uint32_t)(r*144 + gi*16);
            CP16(bS + off2, W + (size_t)r*DFFc + k0 + (gi<<3));
        }
    };

    int warp = tid >> 5;
    int wm = warp & 1, wn = warp >> 1;
    wmma::fragment<wmma::accumulator,16,16,16,float> acc[2][4];
    #pragma unroll
    for (int i = 0; i < 2; i++)
        #pragma unroll
        for (int j = 0; j < 4; j++) wmma::fill_fragment(acc[i][j], 0.f);

    stage(0, dsm); CP_COMMIT();

    const int KC = DFFc / 64;   // 64
    for (int c0 = 0; c0 < KC; c0++) {
        CP_WAIT0();
        __syncthreads();
        if (c0 + 1 < KC) { stage(c0 + 1, dsm + (size_t)((c0+1)&1)*BUF_BYTES); CP_COMMIT(); }
        char* cur = dsm + (size_t)(c0 & 1) * BUF_BYTES;
        __half (*AsHi)[72] = (__half(*)[72])(cur + SM_AHI);
        __half (*AsLo)[72] = (__half(*)[72])(cur + SM_ALO);
        __half (*Bs)[72]   = (__half(*)[72])(cur + SM_B);
        #pragma unroll
        for (int kk = 0; kk < 64; kk += 16) {
            wmma::fragment<wmma::matrix_a,16,16,16,__half,wmma::row_major> aHi[2], aLo[2];
            #pragma unroll
            for (int i = 0; i < 2; i++) {
                wmma::load_matrix_sync(aHi[i], &AsHi[wm*32 + i*16][kk], 72);
                wmma::load_matrix_sync(aLo[i], &AsLo[wm*32 + i*16][kk], 72);
            }
            #pragma unroll
            for (int j = 0; j < 4; j++) {
                wmma::fragment<wmma::matrix_b,16,16,16,__half,wmma::col_major> b;
                wmma::load_matrix_sync(b, &Bs[wn*64 + j*16][kk], 72);
                #pragma unroll
                for (int i = 0; i < 2; i++) {
                    wmma::mma_sync(acc[i][j], aHi[i], b, acc[i][j]);
                    wmma::mma_sync(acc[i][j], aLo[i], b, acc[i][j]);
                }
            }
        }
    }
    __syncthreads();

    float (*Cs)[260] = (float(*)[260])dsm;
    #pragma unroll
    for (int i = 0; i < 2; i++)
        #pragma unroll
        for (int j = 0; j < 4; j++)
            wmma::store_matrix_sync(&Cs[wm*32 + i*16][wn*64 + j*16], acc[i][j], 260, wmma::mem_row_major);
    __syncthreads();

    float g2 = g_g2[e];
    // vectorized: 2 adjacent columns per thread -> float2 stores
    for (int idx = tid; idx < 64*128; idx += 256) {
        int r = idx >> 7, c = (idx & 127) << 1;
        int sc = slots[r];
        if (sc < 0) continue;
        float2 v = make_float2(g2 * Cs[r][c], g2 * Cs[r][c + 1]);
        *reinterpret_cast<float2*>(&g_osl[(size_t)sc*Dc + n0 + c]) = v;
    }
}

// ---------------- combine (resets g_cnt; final step writes out) ----------------
__global__ void combine_kernel(const float* __restrict__ comp, const float* __restrict__ normw,
                               const float* __restrict__ x, float* __restrict__ out, int mode) {
    int t = blockIdx.x, tid = threadIdx.x;
    if (t == 0 && tid < Ec) g_cnt[tid] = 0;
    if (!(comp[t] > 0.5f)) {
        if (mode == 1) {
            #pragma unroll
            for (int i = 0; i < 4; i++) {
                int d = tid + i*256;
                out[(size_t)t*Dc + d] = x[(size_t)t*Dc + d];
            }
        }
        return;
    }
    int se[4];
    #pragma unroll
    for (int k = 0; k < 4; k++) se[k] = g_sel[t*4 + k];
    int ord[4] = {0,1,2,3};
    #pragma unroll
    for (int a = 0; a < 3; a++)
        #pragma unroll
        for (int b = a+1; b < 4; b++)
            if (se[ord[b]] < se[ord[a]]) { int tmp = ord[a]; ord[a] = ord[b]; ord[b] = tmp; }
    float y[4]; float ss = 0.f;
    #pragma unroll
    for (int i = 0; i < 4; i++) {
        int d = tid + i*256;
        float s = g_osl[(size_t)(t*4 + ord[0])*Dc + d];
        s += g_osl[(size_t)(t*4 + ord[1])*Dc + d];
        s += g_osl[(size_t)(t*4 + ord[2])*Dc + d];
        s += g_osl[(size_t)(t*4 + ord[3])*Dc + d];
        float prev = (mode == 2) ? x[(size_t)t*Dc + d] : g_state[(size_t)t*Dc + d];
        float v = s + prev;
        y[i] = v; ss += v*v;
    }
    int lane = tid & 31, wp = tid >> 5;
    for (int o = 16; o > 0; o >>= 1) ss += __shfl_down_sync(0xffffffffu, ss, o);
    __shared__ float ws[8];
    __shared__ float svar;
    if (lane == 0) ws[wp] = ss;
    __syncthreads();
    if (tid == 0) {
        float s2 = 0.f;
        for (int w = 0; w < 8; w++) s2 += ws[w];
        svar = s2 * (1.f / (float)Dc);
    }
    __syncthreads();
    float rinv = rsqrtf(svar + 1e-6f);
    #pragma unroll
    for (int i = 0; i < 4; i++) {
        int d = tid + i*256;
        float val = normw[d] * y[i] * rinv;
        if (mode == 1) out[(size_t)t*Dc + d] = val;
        else           g_state[(size_t)t*Dc + d] = val;
    }
}

// ---------------- launch ----------------
// combine mode: 2 = step 0 (residual from x), 0 = middle steps, 1 = final (write out)
extern "C" void kernel_launch(void* const* d_in, const int* in_sizes, int n_in,
                              void* d_out, int out_size) {
    const float* x    = (const float*)d_in[0];
    const float* comp = (const float*)d_in[1];
    const float* gw   = (const float*)d_in[2];
    const float* w1   = (const float*)d_in[3];
    const float* w2   = (const float*)d_in[4];
    const float* temb = (const float*)d_in[5];
    const float* nw   = (const float*)d_in[6];
    float* out = (float*)d_out;

    cudaFuncSetAttribute(ffn1_kernel, cudaFuncAttributeMaxDynamicSharedMemorySize, DSM_BYTES);
    cudaFuncSetAttribute(ffn2_kernel, cudaFuncAttributeMaxDynamicSharedMemorySize, DSM_BYTES);

    abs_partial_kernel<<<dim3(1024, 32), 256>>>(w1, w2);
    quant_gate_kernel<<<16385, 256>>>(w1, w2, gw);

    for (int s = 0; s < STEPSc; s++) {
        route_kernel<<<Tc, 128>>>(comp, temb, s, x);
        ffn1_kernel<<<dim3(MBLK, DFFc/256, Ec), 256, DSM_BYTES>>>();
        ffn2_kernel<<<dim3(MBLK, Dc/256, Ec), 256, DSM_BYTES>>>();
        int mode = (s == 0) ? 2 : (s == STEPSc-1 ? 1 : 0);
        combine_kernel<<<Tc, 256>>>(comp, nw, x, out, mode);
    }
}